// round 10
// baseline (speedup 1.0000x reference)
#include <cuda_runtime.h>
#include <cstdint>

// Gated delta rule: S_t = S_{t-1} @ A_t + B_t.  T=128, 64 chains, D=64.
// 128 CTAs (2 per chain, 32 rows) x 128 threads, thread tile 4 rows x 4 cols.
// R10 = passing R6 kernel + A-operand shuffle dedup ONLY:
//   A smem rows padded to 320 B; per 8-k block each lane does one uniform
//   LDS.128 (distinct k/col-group data), per k the 4 A values are routed by
//   __shfl_sync. A wavefronts: 4/warp/k -> 0.5/warp/k. S path identical to R6.

#define T_DIM 128
#define BH 64
#define D 64
#define ROWS 32
#define THREADS 128
#define TSTRIDE (BH * D * D)
#define SROW 36
#define ASTRIDE 320                         // padded A row bytes
#define A_BYTES (D * ASTRIDE)               // 20480
#define S_BYTES (D * SROW * 4)              // 9216
#define SMEM_BYTES (2 * A_BYTES + 2 * S_BYTES)   // 59392

__device__ __forceinline__ uint32_t smem_u32(const void* p) {
    return (uint32_t)__cvta_generic_to_shared(p);
}
__device__ __forceinline__ unsigned long long pk2(float lo, float hi) {
    unsigned long long r;
    asm("mov.b64 %0,{%1,%2};" : "=l"(r) : "f"(lo), "f"(hi));
    return r;
}
__device__ __forceinline__ unsigned long long f2fma(unsigned long long a,
                                                    unsigned long long b,
                                                    unsigned long long c) {
    unsigned long long d;
    asm("fma.rn.f32x2 %0,%1,%2,%3;" : "=l"(d) : "l"(a), "l"(b), "l"(c));
    return d;
}

__global__ void __launch_bounds__(THREADS, 1) gdr_kernel(
    const float* __restrict__ A,
    const float* __restrict__ Bm,
    const float* __restrict__ S0,
    float* __restrict__ out)
{
    extern __shared__ char smem[];
    float* Ab0 = (float*)smem;                           // 20480 B
    float* Ab1 = (float*)(smem + A_BYTES);               // 20480 B
    float* Sb0 = (float*)(smem + 2 * A_BYTES);           // 9216 B, [k][r] pad 36
    float* Sb1 = (float*)(smem + 2 * A_BYTES + S_BYTES);

    const int tid   = threadIdx.x;
    const int lane  = tid & 31;
    const int w     = tid >> 5;      // warp id; warp covers cols 16w..16w+15
    const int chain = blockIdx.x >> 1;
    const int half  = blockIdx.x & 1;
    const int r0base = half * ROWS;

    const int rg = tid & 7;          // rows 4rg..4rg+3
    const int cg = tid >> 3;         // 0..15
    const int c0 = cg * 4;
    const int r0 = rg * 4;

    const int om = tid & 15;         // out-store: row pair 2om,2om+1
    const int ocg = tid >> 4;        // col group *8

    const long chainOff = (long)chain * (D * D);

    // shuffle sources: loader lane q8*4 + x holds k=q8, col-group x
    int srcA[8];
    #pragma unroll
    for (int q = 0; q < 8; q++) srcA[q] = q * 4 + (lane >> 3);

    // uniform A-loader lane offset: k = lane>>2 (within 8-k block),
    // cols 16w + (lane&3)*4
    const uint32_t aLaneOff = (uint32_t)((lane >> 2) * ASTRIDE +
                                         (lane & 3) * 16 + w * 64);

    // ---- prologue: A[0] via cp.async into padded layout ----
    {
        const float* g = A + chainOff + tid * 4;
        #pragma unroll
        for (int i = 0; i < 8; i++) {
            int kk = (tid >> 4) + i * 8;
            uint32_t dst = smem_u32(Ab0) + kk * ASTRIDE + (tid & 15) * 16;
            asm volatile("cp.async.cg.shared.global [%0],[%1],16;"
                         :: "r"(dst), "l"(g + i * 512));
        }
        asm volatile("cp.async.commit_group;");
    }

    // Bm[0] -> registers (4 rows x 4 cols)
    float4 q0, q1, q2, q3;
    {
        const float* g = Bm + chainOff + (long)(r0base + r0) * D + c0;
        q0 = *(const float4*)(g);
        q1 = *(const float4*)(g + D);
        q2 = *(const float4*)(g + 2 * D);
        q3 = *(const float4*)(g + 3 * D);
    }

    // Init Sb0[k*SROW + r] = S0[r][k]
    {
        int rl = tid & 31;
        int kb = (tid >> 5) * 16;
        const float* g = S0 + chainOff + (long)(r0base + rl) * D + kb;
        #pragma unroll
        for (int kk = 0; kk < 16; kk++)
            Sb0[(kb + kk) * SROW + rl] = g[kk];
    }

    // ---- main time loop ----
    for (int t = 0; t < T_DIM; t++) {
        asm volatile("cp.async.wait_group 0;" ::: "memory");
        __syncthreads();

        const int cur = t & 1;
        float* Acur  = cur ? Ab1 : Ab0;
        float* Anext = cur ? Ab0 : Ab1;
        float* Scur  = cur ? Sb1 : Sb0;
        float* Snext = cur ? Sb0 : Sb1;

        // prefetch A[t+1] (padded dst)
        if (t + 1 < T_DIM) {
            const float* g = A + (long)(t + 1) * TSTRIDE + chainOff + tid * 4;
            #pragma unroll
            for (int i = 0; i < 8; i++) {
                int kk = (tid >> 4) + i * 8;
                uint32_t dst = smem_u32(Anext) + kk * ASTRIDE + (tid & 15) * 16;
                asm volatile("cp.async.cg.shared.global [%0],[%1],16;"
                             :: "r"(dst), "l"(g + i * 512));
            }
            asm volatile("cp.async.commit_group;");
        }

        // deferred out-store of step t-1 (reads Scur = S_{t-1})
        if (t > 0) {
            uint32_t rb = smem_u32(Scur) + om * 8;
            float v0,v1,v2,v3,v4,v5,v6,v7,v8,v9,v10,v11,v12,v13,v14,v15;
            #define OLD(i, lo, hi) \
                asm("ld.shared.v2.f32 {%0,%1},[%2];" : "=f"(lo), "=f"(hi) \
                    : "r"(rb + (ocg * 8 + i) * (SROW * 4)))
            OLD(0, v0, v1);  OLD(1, v2, v3);  OLD(2, v4, v5);  OLD(3, v6, v7);
            OLD(4, v8, v9);  OLD(5, v10, v11); OLD(6, v12, v13); OLD(7, v14, v15);
            #undef OLD
            float* o = out + (long)(t - 1) * TSTRIDE + chainOff
                     + (long)(r0base + 2 * om) * D + ocg * 8;
            *(float4*)(o)     = make_float4(v0, v2, v4, v6);
            *(float4*)(o + 4) = make_float4(v8, v10, v12, v14);
            *(float4*)(o + D)     = make_float4(v1, v3, v5, v7);
            *(float4*)(o + D + 4) = make_float4(v9, v11, v13, v15);
        }

        // acc := Bm[t] (row-pair packed per column)
        unsigned long long aA0, aA1, aA2, aA3, aB0, aB1, aB2, aB3;
        aA0 = pk2(q0.x, q1.x); aA1 = pk2(q0.y, q1.y);
        aA2 = pk2(q0.z, q1.z); aA3 = pk2(q0.w, q1.w);
        aB0 = pk2(q2.x, q3.x); aB1 = pk2(q2.y, q3.y);
        aB2 = pk2(q2.z, q3.z); aB3 = pk2(q2.w, q3.w);

        // prefetch Bm[t+1]
        if (t + 1 < T_DIM) {
            const float* g = Bm + (long)(t + 1) * TSTRIDE + chainOff
                           + (long)(r0base + r0) * D + c0;
            q0 = *(const float4*)(g);
            q1 = *(const float4*)(g + D);
            q2 = *(const float4*)(g + 2 * D);
            q3 = *(const float4*)(g + 3 * D);
        }

        // ---- k-loop: 8 blocks of 8 k; S per-k LDS (as R6), A via shuffle ----
        const uint32_t sA = smem_u32(Scur) + r0 * 4;
        const uint32_t aU = smem_u32(Acur) + aLaneOff;

        #pragma unroll
        for (int b8 = 0; b8 < 8; b8++) {
            // uniform A load: lane holds A[k=b8*8+(lane>>2)][16w+(lane&3)*4 ..+3]
            float au0, au1, au2, au3;
            asm("ld.shared.v4.f32 {%0,%1,%2,%3},[%4];"
                : "=f"(au0), "=f"(au1), "=f"(au2), "=f"(au3)
                : "r"(aU + b8 * (8 * ASTRIDE)));

            #pragma unroll
            for (int q8 = 0; q8 < 8; q8++) {
                const int k = b8 * 8 + q8;
                unsigned long long svx, svy;
                asm("ld.shared.v2.u64 {%0,%1},[%2];"
                    : "=l"(svx), "=l"(svy) : "r"(sA + k * (SROW * 4)));
                float a0 = __shfl_sync(0xffffffffu, au0, srcA[q8]);
                float a1 = __shfl_sync(0xffffffffu, au1, srcA[q8]);
                float a2 = __shfl_sync(0xffffffffu, au2, srcA[q8]);
                float a3 = __shfl_sync(0xffffffffu, au3, srcA[q8]);
                unsigned long long d0 = pk2(a0, a0);
                unsigned long long d1 = pk2(a1, a1);
                unsigned long long d2 = pk2(a2, a2);
                unsigned long long d3 = pk2(a3, a3);
                aA0 = f2fma(svx, d0, aA0);
                aA1 = f2fma(svx, d1, aA1);
                aA2 = f2fma(svx, d2, aA2);
                aA3 = f2fma(svx, d3, aA3);
                aB0 = f2fma(svy, d0, aB0);
                aB1 = f2fma(svy, d1, aB1);
                aB2 = f2fma(svy, d2, aB2);
                aB3 = f2fma(svy, d3, aB3);
            }
        }

        // Snew -> Snext[c][r]: acc pairs are already the [c][r0..r0+4] layout
        {
            uint32_t stB = smem_u32(Snext) + c0 * (SROW * 4) + r0 * 4;
            asm volatile("st.shared.v2.u64 [%0],{%1,%2};"
                         :: "r"(stB), "l"(aA0), "l"(aB0));
            asm volatile("st.shared.v2.u64 [%0],{%1,%2};"
                         :: "r"(stB + SROW * 4), "l"(aA1), "l"(aB1));
            asm volatile("st.shared.v2.u64 [%0],{%1,%2};"
                         :: "r"(stB + 2 * SROW * 4), "l"(aA2), "l"(aB2));
            asm volatile("st.shared.v2.u64 [%0],{%1,%2};"
                         :: "r"(stB + 3 * SROW * 4), "l"(aA3), "l"(aB3));
        }
    }

    // final out-store for t = T-1
    __syncthreads();
    {
        float* Slast = (T_DIM & 1) ? Sb1 : Sb0;
        uint32_t rb = smem_u32(Slast) + om * 8;
        float v0,v1,v2,v3,v4,v5,v6,v7,v8,v9,v10,v11,v12,v13,v14,v15;
        #define OLD(i, lo, hi) \
            asm("ld.shared.v2.f32 {%0,%1},[%2];" : "=f"(lo), "=f"(hi) \
                : "r"(rb + (ocg * 8 + i) * (SROW * 4)))
        OLD(0, v0, v1);  OLD(1, v2, v3);  OLD(2, v4, v5);  OLD(3, v6, v7);
        OLD(4, v8, v9);  OLD(5, v10, v11); OLD(6, v12, v13); OLD(7, v14, v15);
        #undef OLD
        float* o = out + (long)(T_DIM - 1) * TSTRIDE + chainOff
                 + (long)(r0base + 2 * om) * D + ocg * 8;
        *(float4*)(o)     = make_float4(v0, v2, v4, v6);
        *(float4*)(o + 4) = make_float4(v8, v10, v12, v14);
        *(float4*)(o + D)     = make_float4(v1, v3, v5, v7);
        *(float4*)(o + D + 4) = make_float4(v9, v11, v13, v15);
    }
}

extern "C" void kernel_launch(void* const* d_in, const int* in_sizes, int n_in,
                              void* d_out, int out_size) {
    const float* A  = (const float*)d_in[0];
    const float* Bm = (const float*)d_in[1];
    const float* S0 = (const float*)d_in[2];
    float* out = (float*)d_out;
    (void)in_sizes; (void)n_in; (void)out_size;

    cudaFuncSetAttribute(gdr_kernel,
                         cudaFuncAttributeMaxDynamicSharedMemorySize,
                         SMEM_BYTES);
    gdr_kernel<<<BH * 2, THREADS, SMEM_BYTES>>>(A, Bm, S0, out);
}